// round 13
// baseline (speedup 1.0000x reference)
#include <cuda_runtime.h>

// SSIM loss, vertical-first separable blur, f32x2 with SHARED packed windows:
//   V: thread-per-column, FIELD-packed rings (i1,i2)/(i1^2+i2^2,i1*i2),
//      22 FMA2/row in 4 chains, scalar STS into SoA field buffers.
//   H: 4 px/thread; per field load window as ull2 (16B-stride LDS.128,
//      conflict-free); 7 even-offset packed operands FREE, 6 odd built once
//      and shared by both pixel-pairs; 22 FMA2/px; packed SSIM.
// Inputs: 2x [16,3,512,512] fp32. Output: 1 fp32 scalar.

typedef unsigned long long ull;
typedef ulonglong2 ull2;

#define NTHR    160
#define TILE_W  128
#define TILE_H  16
#define RAD     5
#define KW      11
#define VCOLS   (TILE_W + 2 * RAD)   // 138
#define VSTRIDE 140                  // floats per row, 16B aligned
#define HH      512
#define WW      512
#define PLANES  48
#define GX      (WW / TILE_W)        // 4
#define GY      (HH / TILE_H)        // 32
#define NBLK    (GX * GY * PLANES)   // 6144

__device__ float        g_partials[NBLK];
__device__ unsigned int g_count = 0;

// Gaussian(sigma=1.5) 11 taps, normalized.
__device__ __forceinline__ constexpr float GW(int k) {
    return (k == 0 || k == 10) ? 0.00102838f
         : (k == 1 || k == 9)  ? 0.00759877f
         : (k == 2 || k == 8)  ? 0.03600075f
         : (k == 3 || k == 7)  ? 0.10936082f
         : (k == 4 || k == 6)  ? 0.21300554f
         :                       0.26601172f;
}

// ---- f32x2 helpers ----
__device__ __forceinline__ ull F2(float a, float b) {
    ull r; asm("mov.b64 %0,{%1,%2};" : "=l"(r) : "f"(a), "f"(b)); return r;
}
__device__ __forceinline__ void UF2(ull v, float& a, float& b) {
    asm("mov.b64 {%0,%1},%2;" : "=f"(a), "=f"(b) : "l"(v));
}
__device__ __forceinline__ ull FMA2(ull a, ull b, ull c) {
    ull r; asm("fma.rn.f32x2 %0,%1,%2,%3;" : "=l"(r) : "l"(a), "l"(b), "l"(c)); return r;
}
__device__ __forceinline__ ull MUL2(ull a, ull b) {
    ull r; asm("mul.rn.f32x2 %0,%1,%2;" : "=l"(r) : "l"(a), "l"(b)); return r;
}
__device__ __forceinline__ ull ADD2(ull a, ull b) {
    ull r; asm("add.rn.f32x2 %0,%1,%2;" : "=l"(r) : "l"(a), "l"(b)); return r;
}

__global__ void __launch_bounds__(NTHR, 5)
ssim_main(const float* __restrict__ img1, const float* __restrict__ img2,
          float* __restrict__ out)
{
    // Scalar SoA field buffers: [field][row][col].
    __shared__ __align__(16) float smf[4][TILE_H][VSTRIDE];

    const int tid   = threadIdx.x;
    const int x0    = blockIdx.x * TILE_W;
    const int y0    = blockIdx.y * TILE_H;
    const int plane = blockIdx.z;
    const size_t pbase = (size_t)plane * (HH * WW);

    ull w2[6];
    #pragma unroll
    for (int k = 0; k < 6; ++k) w2[k] = F2(GW(k), GW(k));
    const ull ONE2 = F2(1.f, 1.f);

    // ============ Vertical phase: field-packed f32x2 rings (R8) ============
    if (tid < VCOLS) {
        const int gx  = x0 + tid - RAD;
        const bool vx = ((unsigned)gx < WW);
        const int gxc = min(max(gx, 0), WW - 1);
        const float* __restrict__ p1 = img1 + pbase + gxc;
        const float* __restrict__ p2 = img2 + pbase + gxc;

        ull rab[KW];   // (i1, i2)
        ull rsp[KW];   // (i1^2+i2^2, i1*i2)
        float ca, cb;

        auto loadrow = [&](int i, float& a, float& b) {
            int gy = y0 + i - RAD;
            bool ok = vx && ((unsigned)gy < HH);
            int gyc = min(max(gy, 0), HH - 1);
            size_t off = (size_t)gyc * WW;
            a = ok ? __ldg(p1 + off) : 0.f;
            b = ok ? __ldg(p2 + off) : 0.f;
        };

        #pragma unroll
        for (int i = 0; i < KW - 1; ++i) {
            float a, b; loadrow(i, a, b);
            rab[i] = F2(a, b);
            rsp[i] = F2(fmaf(a, a, b * b), a * b);
        }
        loadrow(KW - 1, ca, cb);

        #pragma unroll
        for (int u = 0; u < TILE_H; ++u) {
            const int sl = (u + KW - 1) % KW;
            rab[sl] = F2(ca, cb);
            rsp[sl] = F2(fmaf(ca, ca, cb * cb), ca * cb);
            if (u < TILE_H - 1) loadrow(u + KW, ca, cb);

            ull ma = 0, mb = 0, qa = 0, qb = 0;   // dual chains
            #pragma unroll
            for (int j = 0; j < KW; ++j) {
                const int s = (u + j) % KW;            // compile-time
                const ull wj = w2[(j < 6) ? j : 10 - j];
                if (j & 1) { mb = FMA2(wj, rab[s], mb); qb = FMA2(wj, rsp[s], qb); }
                else       { ma = FMA2(wj, rab[s], ma); qa = FMA2(wj, rsp[s], qa); }
            }
            ull m = FMA2(ONE2, ma, mb);
            ull q = FMA2(ONE2, qa, qb);
            float m1, m2, qs, q12;
            UF2(m, m1, m2);    // free: register-pair halves
            UF2(q, qs, q12);
            smf[0][u][tid] = m1;
            smf[1][u][tid] = m2;
            smf[2][u][tid] = qs;
            smf[3][u][tid] = q12;
        }
    }
    __syncthreads();

    // ========== Horizontal + SSIM: shared packed windows, 4 px/thread ======
    float acc = 0.f;
    if (tid < 128) {
        const int cg = tid & 31;    // output cols 4cg..4cg+3
        const int rg = tid >> 5;    // row slot

        const ull NEG1 = F2(-1.f, -1.f);
        const ull TWO2 = F2(2.f, 2.f);
        const ull C1v  = F2(1e-4f, 1e-4f);
        const ull C2v  = F2(9e-4f, 9e-4f);

        #pragma unroll 1
        for (int rr = 0; rr < 4; ++rr) {
            const int r = rr * 4 + rg;

            // Results: 2 pixel-pairs per field.
            ull am1[2], am2[2], aqs[2], aq12[2];

            #pragma unroll
            for (int f = 0; f < 4; ++f) {
                // Window floats cv[0..15] (need 0..12) as 4 LDS.128 (16B stride).
                const ull2* __restrict__ rp2 =
                    reinterpret_cast<const ull2*>(&smf[f][r][0]) + 2 * 0;  // base
                const ull2* __restrict__ pw =
                    reinterpret_cast<const ull2*>(&smf[f][r][0]);
                ull2 a0 = pw[2 * cg + 0];
                ull2 a1 = pw[2 * cg + 1];
                // NOTE: [2cg] in ull2 units = float index 4cg; stride 16B? ull2 =
                // 16B so consecutive lanes at 2cg differ by 32B -> WRONG.
                (void)rp2;
                // Correct: load as two ull2 from float4-aligned addresses:
                // float idx 4cg -> ull2 idx cg (ull2 = 4 floats). Redo:
                a0 = pw[cg + 0];       // cv0..cv3   -> pairs e0=(0,1), e1=(2,3)
                a1 = pw[cg + 1];       // cv4..cv7
                ull2 a2 = pw[cg + 2];  // cv8..cv11
                ull2 a3 = pw[cg + 3];  // cv12..cv15

                // Even-offset packed operands (FREE: natural reg pairs).
                ull e0 = a0.x, e1 = a0.y, e2 = a1.x, e3 = a1.y;
                ull e4 = a2.x, e5 = a2.y, e6 = a3.x;

                // Odd-offset packs (6, shared by both pairs).
                float c0, c1, c2, c3, c4, c5, c6, c7, c8, c9, c10, c11, c12, c13;
                UF2(e0, c0, c1);   UF2(e1, c2, c3);
                UF2(e2, c4, c5);   UF2(e3, c6, c7);
                UF2(e4, c8, c9);   UF2(e5, c10, c11);
                UF2(e6, c12, c13);
                ull o1  = F2(c1, c2);
                ull o3  = F2(c3, c4);
                ull o5  = F2(c5, c6);
                ull o7  = F2(c7, c8);
                ull o9  = F2(c9, c10);
                ull o11 = F2(c11, c12);

                const ull w[13] = { e0, o1, e1, o3, e2, o5, e3,
                                    o7, e4, o9, e5, o11, e6 };

                ull* d0 = (f == 0) ? am1 : (f == 1) ? am2 : (f == 2) ? aqs : aq12;
                #pragma unroll
                for (int p = 0; p < 2; ++p) {
                    ull s0 = 0, s1 = 0;   // dual chains
                    #pragma unroll
                    for (int k = 0; k < KW; ++k) {
                        const ull wj = w2[(k < 6) ? k : 10 - k];
                        if (k & 1) s1 = FMA2(wj, w[2 * p + k], s1);
                        else       s0 = FMA2(wj, w[2 * p + k], s0);
                    }
                    d0[p] = FMA2(ONE2, s0, s1);
                }
            }

            // Packed SSIM per pixel-pair.
            #pragma unroll
            for (int p = 0; p < 2; ++p) {
                ull mu12 = MUL2(am1[p], am2[p]);
                ull mu1s = MUL2(am1[p], am1[p]);
                ull mu2s = MUL2(am2[p], am2[p]);
                ull s12  = FMA2(mu12, NEG1, aq12[p]);
                ull n1   = FMA2(TWO2, mu12, C1v);
                ull n2   = FMA2(TWO2, s12,  C2v);
                ull S    = ADD2(mu1s, mu2s);
                ull d1   = ADD2(S, C1v);
                ull d2   = ADD2(FMA2(S, NEG1, aqs[p]), C2v);
                ull num  = MUL2(n1, n2);
                ull den  = MUL2(d1, d2);
                float nx, ny, dx, dy;
                UF2(num, nx, ny);
                UF2(den, dx, dy);
                acc += __fdividef(nx, dx);
                acc += __fdividef(ny, dy);
            }
        }
    }

    // ================= Reduction =================
    #pragma unroll
    for (int o = 16; o; o >>= 1)
        acc += __shfl_xor_sync(0xFFFFFFFFu, acc, o);

    __shared__ float ws[NTHR / 32];
    if ((tid & 31) == 0) ws[tid >> 5] = acc;
    __syncthreads();

    const int bid = (blockIdx.z * GY + blockIdx.y) * GX + blockIdx.x;
    __shared__ unsigned int is_last;
    if (tid == 0) {
        float bs = 0.f;
        #pragma unroll
        for (int i = 0; i < NTHR / 32; ++i) bs += ws[i];
        __stcg(&g_partials[bid], bs);
        __threadfence();
        is_last = (atomicAdd(&g_count, 1u) == (unsigned)(NBLK - 1));
    }
    __syncthreads();

    if (is_last) {
        double s = 0.0;
        for (int i = tid; i < NBLK; i += NTHR)
            s += (double)__ldcg(&g_partials[i]);
        #pragma unroll
        for (int o = 16; o; o >>= 1)
            s += __shfl_xor_sync(0xFFFFFFFFu, s, o);
        __shared__ double wd[NTHR / 32];
        if ((tid & 31) == 0) wd[tid >> 5] = s;
        __syncthreads();
        if (tid == 0) {
            double bs = 0.0;
            #pragma unroll
            for (int i = 0; i < NTHR / 32; ++i) bs += wd[i];
            double n = (double)PLANES * HH * WW;
            out[0] = (float)(1.0 - bs / n);
            g_count = 0;   // reset for next graph replay
        }
    }
}

extern "C" void kernel_launch(void* const* d_in, const int* in_sizes, int n_in,
                              void* d_out, int out_size)
{
    (void)in_sizes; (void)n_in; (void)out_size;
    const float* img1 = (const float*)d_in[0];
    const float* img2 = (const float*)d_in[1];
    float* out = (float*)d_out;

    dim3 grid(GX, GY, PLANES);
    ssim_main<<<grid, NTHR>>>(img1, img2, out);
}

// round 14
// speedup vs baseline: 1.1135x; 1.1135x over previous
#include <cuda_runtime.h>

// SSIM loss, vertical-first separable blur — R4 scalar structure +
// block-uniform y specialization:
//   V: thread-per-column vertical 11-tap of {i1,i2,i1^2+i2^2,i1*i2}.
//      yclean blocks (30/32): static LDG offsets, no clamp math (x via select).
//      y-edge blocks (2/32): compact rolled shift-ring with full clamping.
//   H: 4 px/thread, conflict-free float4 smem reads, imm-form FFMA taps,
//      scalar SSIM + fast divide; fused deterministic mean.
// Inputs: 2x [16,3,512,512] fp32. Output: 1 fp32 scalar.

#define NTHR    160
#define TILE_W  128
#define TILE_H  16
#define RAD     5
#define KW      11
#define VCOLS   (TILE_W + 2 * RAD)   // 138
#define VSTRIDE 140                  // floats per row, 16B aligned
#define HH      512
#define WW      512
#define PLANES  48
#define GX      (WW / TILE_W)        // 4
#define GY      (HH / TILE_H)        // 32
#define NBLK    (GX * GY * PLANES)   // 6144

__device__ float        g_partials[NBLK];
__device__ unsigned int g_count = 0;

// Gaussian(sigma=1.5) 11 taps, normalized; literals -> immediate-form FFMA.
__device__ __forceinline__ constexpr float GW(int k) {
    return (k == 0 || k == 10) ? 0.00102838f
         : (k == 1 || k == 9)  ? 0.00759877f
         : (k == 2 || k == 8)  ? 0.03600075f
         : (k == 3 || k == 7)  ? 0.10936082f
         : (k == 4 || k == 6)  ? 0.21300554f
         :                       0.26601172f;
}

__global__ void __launch_bounds__(NTHR, 5)
ssim_main(const float* __restrict__ img1, const float* __restrict__ img2,
          float* __restrict__ out)
{
    // SoA field buffers: [field][row][col], rows 16B-aligned.
    __shared__ __align__(16) float smf[4][TILE_H][VSTRIDE];

    const int tid   = threadIdx.x;
    const int x0    = blockIdx.x * TILE_W;
    const int y0    = blockIdx.y * TILE_H;
    const int plane = blockIdx.z;
    const size_t pbase = (size_t)plane * (HH * WW);

    // ================= Vertical phase =================
    if (tid < VCOLS) {
        const int gx  = x0 + tid - RAD;
        const bool vx = ((unsigned)gx < WW);
        const int gxc = min(max(gx, 0), WW - 1);
        const float* __restrict__ p1 = img1 + pbase + gxc;
        const float* __restrict__ p2 = img2 + pbase + gxc;

        float ra[KW], rb[KW], rs[KW], rp[KW];

        // Rows touched: y0-5 .. y0+25; clean iff all within [0, 512).
        if (y0 >= RAD && y0 + TILE_H - 1 + 2 * RAD < HH) {
            // ---------- yclean fast path: static LDG offsets ----------
            const float* __restrict__ b1 = p1 + (size_t)(y0 - RAD) * WW;
            const float* __restrict__ b2 = p2 + (size_t)(y0 - RAD) * WW;

            #pragma unroll
            for (int i = 0; i < KW - 1; ++i) {
                float a = vx ? __ldg(b1 + i * WW) : 0.f;
                float b = vx ? __ldg(b2 + i * WW) : 0.f;
                ra[i] = a; rb[i] = b;
                rs[i] = fmaf(b, b, a * a);
                rp[i] = a * b;
            }
            float ca = vx ? __ldg(b1 + (KW - 1) * WW) : 0.f;
            float cb = vx ? __ldg(b2 + (KW - 1) * WW) : 0.f;

            #pragma unroll
            for (int u = 0; u < TILE_H; ++u) {
                const int sl = (u + KW - 1) % KW;
                ra[sl] = ca; rb[sl] = cb;
                rs[sl] = fmaf(cb, cb, ca * ca);
                rp[sl] = ca * cb;
                if (u < TILE_H - 1) {
                    ca = vx ? __ldg(b1 + (u + KW) * WW) : 0.f;  // interleaved
                    cb = vx ? __ldg(b2 + (u + KW) * WW) : 0.f;
                }

                float m1 = 0.f, m2 = 0.f, qs = 0.f, q12 = 0.f;
                #pragma unroll
                for (int j = 0; j < KW; ++j) {
                    const int s = (u + j) % KW;      // compile-time
                    m1  = fmaf(GW(j), ra[s], m1);
                    m2  = fmaf(GW(j), rb[s], m2);
                    qs  = fmaf(GW(j), rs[s], qs);
                    q12 = fmaf(GW(j), rp[s], q12);
                }
                smf[0][u][tid] = m1;
                smf[1][u][tid] = m2;
                smf[2][u][tid] = qs;
                smf[3][u][tid] = q12;
            }
        } else {
            // ---------- y-edge path (2/32 blocks): compact rolled ----------
            #pragma unroll
            for (int i = 0; i < KW - 1; ++i) {
                int gy = y0 + i - RAD;
                bool ok = vx && ((unsigned)gy < HH);
                int gyc = min(max(gy, 0), HH - 1);
                float a = ok ? __ldg(p1 + (size_t)gyc * WW) : 0.f;
                float b = ok ? __ldg(p2 + (size_t)gyc * WW) : 0.f;
                ra[i] = a; rb[i] = b;
                rs[i] = fmaf(b, b, a * a);
                rp[i] = a * b;
            }

            #pragma unroll 1
            for (int u = 0; u < TILE_H; ++u) {
                int gy = y0 + u + KW - 1 - RAD;
                bool ok = vx && ((unsigned)gy < HH);
                int gyc = min(max(gy, 0), HH - 1);
                float ca = ok ? __ldg(p1 + (size_t)gyc * WW) : 0.f;
                float cb = ok ? __ldg(p2 + (size_t)gyc * WW) : 0.f;
                ra[KW - 1] = ca; rb[KW - 1] = cb;
                rs[KW - 1] = fmaf(cb, cb, ca * ca);
                rp[KW - 1] = ca * cb;

                float m1 = 0.f, m2 = 0.f, qs = 0.f, q12 = 0.f;
                #pragma unroll
                for (int j = 0; j < KW; ++j) {
                    m1  = fmaf(GW(j), ra[j], m1);
                    m2  = fmaf(GW(j), rb[j], m2);
                    qs  = fmaf(GW(j), rs[j], qs);
                    q12 = fmaf(GW(j), rp[j], q12);
                }
                smf[0][u][tid] = m1;
                smf[1][u][tid] = m2;
                smf[2][u][tid] = qs;
                smf[3][u][tid] = q12;

                #pragma unroll
                for (int j = 0; j < KW - 1; ++j) {   // shift ring
                    ra[j] = ra[j + 1]; rb[j] = rb[j + 1];
                    rs[j] = rs[j + 1]; rp[j] = rp[j + 1];
                }
            }
        }
    }
    __syncthreads();

    // ================= Horizontal + SSIM phase (R4 exact) =================
    float acc = 0.f;
    if (tid < 128) {
        const int cg = tid & 31;    // output cols 4cg..4cg+3
        const int rg = tid >> 5;    // row slot

        #pragma unroll 1
        for (int rr = 0; rr < 4; ++rr) {
            const int r = rr * 4 + rg;

            float fm1[4], fm2[4], fqs[4], fq12[4];
            #pragma unroll
            for (int d = 0; d < 4; ++d) { fm1[d] = fm2[d] = fqs[d] = fq12[d] = 0.f; }

            // Per field: 4 float4 loads cover cols 4cg..4cg+15 (need ..+13).
            #pragma unroll
            for (int f = 0; f < 4; ++f) {
                const float4* __restrict__ rp4 =
                    reinterpret_cast<const float4*>(&smf[f][r][0]);
                float4 q0 = rp4[cg + 0];
                float4 q1 = rp4[cg + 1];
                float4 q2 = rp4[cg + 2];
                float4 q3 = rp4[cg + 3];
                float cv[16] = { q0.x, q0.y, q0.z, q0.w,
                                 q1.x, q1.y, q1.z, q1.w,
                                 q2.x, q2.y, q2.z, q2.w,
                                 q3.x, q3.y, q3.z, q3.w };
                float* dst = (f == 0) ? fm1 : (f == 1) ? fm2 : (f == 2) ? fqs : fq12;
                #pragma unroll
                for (int d = 0; d < 4; ++d) {
                    float a = 0.f;
                    #pragma unroll
                    for (int k = 0; k < KW; ++k)
                        a = fmaf(GW(k), cv[d + k], a);
                    dst[d] = a;
                }
            }

            #pragma unroll
            for (int d = 0; d < 4; ++d) {
                float mu12 = fm1[d] * fm2[d];
                float mu1s = fm1[d] * fm1[d];
                float mu2s = fm2[d] * fm2[d];
                float s12  = fq12[d] - mu12;
                float n1   = fmaf(2.f, mu12, 1e-4f);
                float n2   = fmaf(2.f, s12,  9e-4f);
                float ttv  = mu1s + mu2s;
                float d1   = ttv + 1e-4f;
                float d2   = (fqs[d] - ttv) + 9e-4f;
                acc += __fdividef(n1 * n2, d1 * d2);
            }
        }
    }

    // ================= Reduction =================
    #pragma unroll
    for (int o = 16; o; o >>= 1)
        acc += __shfl_xor_sync(0xFFFFFFFFu, acc, o);

    __shared__ float ws[NTHR / 32];
    if ((tid & 31) == 0) ws[tid >> 5] = acc;
    __syncthreads();

    const int bid = (blockIdx.z * GY + blockIdx.y) * GX + blockIdx.x;
    __shared__ unsigned int is_last;
    if (tid == 0) {
        float bs = 0.f;
        #pragma unroll
        for (int i = 0; i < NTHR / 32; ++i) bs += ws[i];
        __stcg(&g_partials[bid], bs);
        __threadfence();
        is_last = (atomicAdd(&g_count, 1u) == (unsigned)(NBLK - 1));
    }
    __syncthreads();

    if (is_last) {
        double s = 0.0;
        for (int i = tid; i < NBLK; i += NTHR)
            s += (double)__ldcg(&g_partials[i]);
        #pragma unroll
        for (int o = 16; o; o >>= 1)
            s += __shfl_xor_sync(0xFFFFFFFFu, s, o);
        __shared__ double wd[NTHR / 32];
        if ((tid & 31) == 0) wd[tid >> 5] = s;
        __syncthreads();
        if (tid == 0) {
            double bs = 0.0;
            #pragma unroll
            for (int i = 0; i < NTHR / 32; ++i) bs += wd[i];
            double n = (double)PLANES * HH * WW;
            out[0] = (float)(1.0 - bs / n);
            g_count = 0;   // reset for next graph replay
        }
    }
}

extern "C" void kernel_launch(void* const* d_in, const int* in_sizes, int n_in,
                              void* d_out, int out_size)
{
    (void)in_sizes; (void)n_in; (void)out_size;
    const float* img1 = (const float*)d_in[0];
    const float* img2 = (const float*)d_in[1];
    float* out = (float*)d_out;

    dim3 grid(GX, GY, PLANES);
    ssim_main<<<grid, NTHR>>>(img1, img2, out);
}

// round 15
// speedup vs baseline: 1.1418x; 1.0255x over previous
#include <cuda_runtime.h>

// SSIM loss, vertical-first separable blur with f32x2 packing (R5 champion)
// + occupancy bump to 6 blocks/SM (30 warps) to fill FMA2 latency stalls:
//   V: thread-per-column, FIELD-packed rings (i1,i2)/(i1^2+i2^2,ab) -> 22 FMA2/row
//   H: 4 px/thread, PIXEL-PAIR packed taps -> 22 FMA2/px, packed SSIM
// Inputs: 2x [16,3,512,512] fp32. Output: 1 fp32 scalar.

typedef unsigned long long ull;

#define NTHR    160
#define TILE_W  128
#define TILE_H  16
#define RAD     5
#define KW      11
#define VCOLS   (TILE_W + 2 * RAD)   // 138
#define VSTRIDE 140                  // floats per row, 16B aligned
#define HH      512
#define WW      512
#define PLANES  48
#define GX      (WW / TILE_W)        // 4
#define GY      (HH / TILE_H)        // 32
#define NBLK    (GX * GY * PLANES)   // 6144

__device__ float        g_partials[NBLK];
__device__ unsigned int g_count = 0;

// Gaussian(sigma=1.5) 11 taps, normalized.
__device__ __forceinline__ constexpr float GW(int k) {
    return (k == 0 || k == 10) ? 0.00102838f
         : (k == 1 || k == 9)  ? 0.00759877f
         : (k == 2 || k == 8)  ? 0.03600075f
         : (k == 3 || k == 7)  ? 0.10936082f
         : (k == 4 || k == 6)  ? 0.21300554f
         :                       0.26601172f;
}

// ---- f32x2 helpers ----
__device__ __forceinline__ ull F2(float a, float b) {
    ull r; asm("mov.b64 %0,{%1,%2};" : "=l"(r) : "f"(a), "f"(b)); return r;
}
__device__ __forceinline__ float FLO(ull v) {
    float a, b; asm("mov.b64 {%0,%1},%2;" : "=f"(a), "=f"(b) : "l"(v)); return a;
}
__device__ __forceinline__ float FHI(ull v) {
    float a, b; asm("mov.b64 {%0,%1},%2;" : "=f"(a), "=f"(b) : "l"(v)); return b;
}
__device__ __forceinline__ ull FMA2(ull a, ull b, ull c) {
    ull r; asm("fma.rn.f32x2 %0,%1,%2,%3;" : "=l"(r) : "l"(a), "l"(b), "l"(c)); return r;
}
__device__ __forceinline__ ull MUL2(ull a, ull b) {
    ull r; asm("mul.rn.f32x2 %0,%1,%2;" : "=l"(r) : "l"(a), "l"(b)); return r;
}
__device__ __forceinline__ ull ADD2(ull a, ull b) {
    ull r; asm("add.rn.f32x2 %0,%1,%2;" : "=l"(r) : "l"(a), "l"(b)); return r;
}

__global__ void __launch_bounds__(NTHR, 6)
ssim_main(const float* __restrict__ img1, const float* __restrict__ img2,
          float* __restrict__ out)
{
    __shared__ __align__(16) float smf[4][TILE_H][VSTRIDE];

    const int tid   = threadIdx.x;
    const int x0    = blockIdx.x * TILE_W;
    const int y0    = blockIdx.y * TILE_H;
    const int plane = blockIdx.z;
    const size_t pbase = (size_t)plane * (HH * WW);

    // 6 distinct packed weights (symmetric kernel).
    ull w2[6];
    #pragma unroll
    for (int k = 0; k < 6; ++k) w2[k] = F2(GW(k), GW(k));

    // ================= Vertical phase (field-packed f32x2) =================
    if (tid < VCOLS) {
        const int gx  = x0 + tid - RAD;
        const bool vx = ((unsigned)gx < WW);
        const int gxc = min(max(gx, 0), WW - 1);
        const float* __restrict__ p1 = img1 + pbase + gxc;
        const float* __restrict__ p2 = img2 + pbase + gxc;

        ull rab[KW];   // (a, b)
        ull rsp[KW];   // (a^2+b^2, a*b)
        float ca, cb;

        auto loadrow = [&](int i, float& a, float& b) {
            int gy = y0 + i - RAD;
            bool ok = vx && ((unsigned)gy < HH);
            int gyc = min(max(gy, 0), HH - 1);
            size_t off = (size_t)gyc * WW;
            a = ok ? __ldg(p1 + off) : 0.f;
            b = ok ? __ldg(p2 + off) : 0.f;
        };

        #pragma unroll
        for (int i = 0; i < KW - 1; ++i) {
            float a, b; loadrow(i, a, b);
            rab[i] = F2(a, b);
            rsp[i] = F2(fmaf(a, a, b * b), a * b);
        }
        loadrow(KW - 1, ca, cb);

        #pragma unroll
        for (int u = 0; u < TILE_H; ++u) {
            const int sl = (u + KW - 1) % KW;
            rab[sl] = F2(ca, cb);
            rsp[sl] = F2(fmaf(ca, ca, cb * cb), ca * cb);
            if (u < TILE_H - 1) loadrow(u + KW, ca, cb);

            ull m = 0, q = 0;   // (m1,m2), (qs,q12)
            #pragma unroll
            for (int j = 0; j < KW; ++j) {
                const int s = (u + j) % KW;            // compile-time
                const ull wj = w2[(j < 6) ? j : 10 - j];
                m = FMA2(wj, rab[s], m);
                q = FMA2(wj, rsp[s], q);
            }
            smf[0][u][tid] = FLO(m);
            smf[1][u][tid] = FHI(m);
            smf[2][u][tid] = FLO(q);
            smf[3][u][tid] = FHI(q);
        }
    }
    __syncthreads();

    // ================= Horizontal + SSIM (pixel-pair f32x2) =================
    float acc = 0.f;
    if (tid < 128) {
        const int cg = tid & 31;    // output cols 4cg..4cg+3
        const int rg = tid >> 5;    // row slot

        const ull NEG1 = F2(-1.f, -1.f);
        const ull TWO2 = F2(2.f, 2.f);
        const ull C1v  = F2(1e-4f, 1e-4f);
        const ull C2v  = F2(9e-4f, 9e-4f);

        #pragma unroll 1
        for (int rr = 0; rr < 4; ++rr) {
            const int r = rr * 4 + rg;

            ull am1[2] = {0, 0}, am2[2] = {0, 0}, aqs[2] = {0, 0}, aq12[2] = {0, 0};

            #pragma unroll
            for (int f = 0; f < 4; ++f) {
                const float4* __restrict__ rp4 =
                    reinterpret_cast<const float4*>(&smf[f][r][0]);
                float4 q0 = rp4[cg + 0];
                float4 q1 = rp4[cg + 1];
                float4 q2 = rp4[cg + 2];
                float4 q3 = rp4[cg + 3];
                float cv[16] = { q0.x, q0.y, q0.z, q0.w,
                                 q1.x, q1.y, q1.z, q1.w,
                                 q2.x, q2.y, q2.z, q2.w,
                                 q3.x, q3.y, q3.z, q3.w };
                ull* dst = (f == 0) ? am1 : (f == 1) ? am2 : (f == 2) ? aqs : aq12;

                #pragma unroll
                for (int p = 0; p < 2; ++p) {          // pixel pairs (0,1), (2,3)
                    ull a = dst[p];
                    #pragma unroll
                    for (int k = 0; k < KW; ++k) {
                        const ull wj = w2[(k < 6) ? k : 10 - k];
                        a = FMA2(wj, F2(cv[2 * p + k], cv[2 * p + k + 1]), a);
                    }
                    dst[p] = a;
                }
            }

            #pragma unroll
            for (int p = 0; p < 2; ++p) {
                ull mu12 = MUL2(am1[p], am2[p]);
                ull mu1s = MUL2(am1[p], am1[p]);
                ull mu2s = MUL2(am2[p], am2[p]);
                ull s12  = FMA2(mu12, NEG1, aq12[p]);  // q12 - mu1*mu2
                ull n1   = FMA2(TWO2, mu12, C1v);
                ull n2   = FMA2(TWO2, s12,  C2v);
                ull aa   = ADD2(mu1s, mu2s);
                ull d1   = ADD2(aa, C1v);
                ull tt   = FMA2(aa, NEG1, aqs[p]);     // qs - (mu1^2+mu2^2)
                ull d2   = ADD2(tt, C2v);
                ull num  = MUL2(n1, n2);
                ull den  = MUL2(d1, d2);
                acc += __fdividef(FLO(num), FLO(den));
                acc += __fdividef(FHI(num), FHI(den));
            }
        }
    }

    // ================= Reduction =================
    #pragma unroll
    for (int o = 16; o; o >>= 1)
        acc += __shfl_xor_sync(0xFFFFFFFFu, acc, o);

    __shared__ float ws[NTHR / 32];
    if ((tid & 31) == 0) ws[tid >> 5] = acc;
    __syncthreads();

    const int bid = (blockIdx.z * GY + blockIdx.y) * GX + blockIdx.x;
    __shared__ unsigned int is_last;
    if (tid == 0) {
        float bs = 0.f;
        #pragma unroll
        for (int i = 0; i < NTHR / 32; ++i) bs += ws[i];
        __stcg(&g_partials[bid], bs);
        __threadfence();
        is_last = (atomicAdd(&g_count, 1u) == (unsigned)(NBLK - 1));
    }
    __syncthreads();

    if (is_last) {
        double s = 0.0;
        for (int i = tid; i < NBLK; i += NTHR)
            s += (double)__ldcg(&g_partials[i]);
        #pragma unroll
        for (int o = 16; o; o >>= 1)
            s += __shfl_xor_sync(0xFFFFFFFFu, s, o);
        __shared__ double wd[NTHR / 32];
        if ((tid & 31) == 0) wd[tid >> 5] = s;
        __syncthreads();
        if (tid == 0) {
            double bs = 0.0;
            #pragma unroll
            for (int i = 0; i < NTHR / 32; ++i) bs += wd[i];
            double n = (double)PLANES * HH * WW;
            out[0] = (float)(1.0 - bs / n);
            g_count = 0;   // reset for next graph replay
        }
    }
}

extern "C" void kernel_launch(void* const* d_in, const int* in_sizes, int n_in,
                              void* d_out, int out_size)
{
    (void)in_sizes; (void)n_in; (void)out_size;
    const float* img1 = (const float*)d_in[0];
    const float* img2 = (const float*)d_in[1];
    float* out = (float*)d_out;

    dim3 grid(GX, GY, PLANES);
    ssim_main<<<grid, NTHR>>>(img1, img2, out);
}

// round 16
// speedup vs baseline: 1.2254x; 1.0732x over previous
#include <cuda_runtime.h>

// SSIM loss, vertical-first separable blur, f32x2 (R5 champion) with
// de-serialized H phase:
//   V: thread-per-column, FIELD-packed rings (i1,i2)/(i1^2+i2^2,ab), 22 FMA2/row.
//   H: 4 px/thread; per field ONE shared 13-entry packed window (explicit CSE),
//      pixel-pairs consume pk[k] / pk[k+2]; DUAL even/odd accumulation chains
//      per pair (depth 6) -> 4 independent FMA2 chains per field.
// Inputs: 2x [16,3,512,512] fp32. Output: 1 fp32 scalar.

typedef unsigned long long ull;

#define NTHR    160
#define TILE_W  128
#define TILE_H  16
#define RAD     5
#define KW      11
#define VCOLS   (TILE_W + 2 * RAD)   // 138
#define VSTRIDE 140                  // floats per row, 16B aligned
#define HH      512
#define WW      512
#define PLANES  48
#define GX      (WW / TILE_W)        // 4
#define GY      (HH / TILE_H)        // 32
#define NBLK    (GX * GY * PLANES)   // 6144

__device__ float        g_partials[NBLK];
__device__ unsigned int g_count = 0;

// Gaussian(sigma=1.5) 11 taps, normalized.
__device__ __forceinline__ constexpr float GW(int k) {
    return (k == 0 || k == 10) ? 0.00102838f
         : (k == 1 || k == 9)  ? 0.00759877f
         : (k == 2 || k == 8)  ? 0.03600075f
         : (k == 3 || k == 7)  ? 0.10936082f
         : (k == 4 || k == 6)  ? 0.21300554f
         :                       0.26601172f;
}

// ---- f32x2 helpers ----
__device__ __forceinline__ ull F2(float a, float b) {
    ull r; asm("mov.b64 %0,{%1,%2};" : "=l"(r) : "f"(a), "f"(b)); return r;
}
__device__ __forceinline__ float FLO(ull v) {
    float a, b; asm("mov.b64 {%0,%1},%2;" : "=f"(a), "=f"(b) : "l"(v)); return a;
}
__device__ __forceinline__ float FHI(ull v) {
    float a, b; asm("mov.b64 {%0,%1},%2;" : "=f"(a), "=f"(b) : "l"(v)); return b;
}
__device__ __forceinline__ ull FMA2(ull a, ull b, ull c) {
    ull r; asm("fma.rn.f32x2 %0,%1,%2,%3;" : "=l"(r) : "l"(a), "l"(b), "l"(c)); return r;
}
__device__ __forceinline__ ull MUL2(ull a, ull b) {
    ull r; asm("mul.rn.f32x2 %0,%1,%2;" : "=l"(r) : "l"(a), "l"(b)); return r;
}
__device__ __forceinline__ ull ADD2(ull a, ull b) {
    ull r; asm("add.rn.f32x2 %0,%1,%2;" : "=l"(r) : "l"(a), "l"(b)); return r;
}

__global__ void __launch_bounds__(NTHR, 5)
ssim_main(const float* __restrict__ img1, const float* __restrict__ img2,
          float* __restrict__ out)
{
    __shared__ __align__(16) float smf[4][TILE_H][VSTRIDE];

    const int tid   = threadIdx.x;
    const int x0    = blockIdx.x * TILE_W;
    const int y0    = blockIdx.y * TILE_H;
    const int plane = blockIdx.z;
    const size_t pbase = (size_t)plane * (HH * WW);

    // 6 distinct packed weights (symmetric kernel).
    ull w2[6];
    #pragma unroll
    for (int k = 0; k < 6; ++k) w2[k] = F2(GW(k), GW(k));

    // ================= Vertical phase (field-packed f32x2, R5) ==============
    if (tid < VCOLS) {
        const int gx  = x0 + tid - RAD;
        const bool vx = ((unsigned)gx < WW);
        const int gxc = min(max(gx, 0), WW - 1);
        const float* __restrict__ p1 = img1 + pbase + gxc;
        const float* __restrict__ p2 = img2 + pbase + gxc;

        ull rab[KW];   // (a, b)
        ull rsp[KW];   // (a^2+b^2, a*b)
        float ca, cb;

        auto loadrow = [&](int i, float& a, float& b) {
            int gy = y0 + i - RAD;
            bool ok = vx && ((unsigned)gy < HH);
            int gyc = min(max(gy, 0), HH - 1);
            size_t off = (size_t)gyc * WW;
            a = ok ? __ldg(p1 + off) : 0.f;
            b = ok ? __ldg(p2 + off) : 0.f;
        };

        #pragma unroll
        for (int i = 0; i < KW - 1; ++i) {
            float a, b; loadrow(i, a, b);
            rab[i] = F2(a, b);
            rsp[i] = F2(fmaf(a, a, b * b), a * b);
        }
        loadrow(KW - 1, ca, cb);

        #pragma unroll
        for (int u = 0; u < TILE_H; ++u) {
            const int sl = (u + KW - 1) % KW;
            rab[sl] = F2(ca, cb);
            rsp[sl] = F2(fmaf(ca, ca, cb * cb), ca * cb);
            if (u < TILE_H - 1) loadrow(u + KW, ca, cb);

            ull m = 0, q = 0;   // (m1,m2), (qs,q12)
            #pragma unroll
            for (int j = 0; j < KW; ++j) {
                const int s = (u + j) % KW;            // compile-time
                const ull wj = w2[(j < 6) ? j : 10 - j];
                m = FMA2(wj, rab[s], m);
                q = FMA2(wj, rsp[s], q);
            }
            smf[0][u][tid] = FLO(m);
            smf[1][u][tid] = FHI(m);
            smf[2][u][tid] = FLO(q);
            smf[3][u][tid] = FHI(q);
        }
    }
    __syncthreads();

    // ========== Horizontal + SSIM: shared pack window, dual chains ==========
    float acc = 0.f;
    if (tid < 128) {
        const int cg = tid & 31;    // output cols 4cg..4cg+3
        const int rg = tid >> 5;    // row slot

        const ull NEG1 = F2(-1.f, -1.f);
        const ull TWO2 = F2(2.f, 2.f);
        const ull C1v  = F2(1e-4f, 1e-4f);
        const ull C2v  = F2(9e-4f, 9e-4f);
        const ull ONE2 = F2(1.f, 1.f);

        #pragma unroll 1
        for (int rr = 0; rr < 4; ++rr) {
            const int r = rr * 4 + rg;

            ull am1[2], am2[2], aqs[2], aq12[2];

            #pragma unroll
            for (int f = 0; f < 4; ++f) {
                const float4* __restrict__ rp4 =
                    reinterpret_cast<const float4*>(&smf[f][r][0]);
                float4 q0 = rp4[cg + 0];
                float4 q1 = rp4[cg + 1];
                float4 q2 = rp4[cg + 2];
                float4 q3 = rp4[cg + 3];
                float cv[16] = { q0.x, q0.y, q0.z, q0.w,
                                 q1.x, q1.y, q1.z, q1.w,
                                 q2.x, q2.y, q2.z, q2.w,
                                 q3.x, q3.y, q3.z, q3.w };

                // Shared packed window: pk[k] = (cv[k], cv[k+1]), k = 0..12.
                ull pk[13];
                #pragma unroll
                for (int k = 0; k < 13; ++k) pk[k] = F2(cv[k], cv[k + 1]);

                ull* dst = (f == 0) ? am1 : (f == 1) ? am2 : (f == 2) ? aqs : aq12;
                #pragma unroll
                for (int p = 0; p < 2; ++p) {          // pixel pairs (0,1), (2,3)
                    ull e = 0, o = 0;                  // dual chains (depth 6/5)
                    #pragma unroll
                    for (int k = 0; k < KW; ++k) {
                        const ull wj = w2[(k < 6) ? k : 10 - k];
                        if (k & 1) o = FMA2(wj, pk[2 * p + k], o);
                        else       e = FMA2(wj, pk[2 * p + k], e);
                    }
                    dst[p] = FMA2(ONE2, e, o);
                }
            }

            #pragma unroll
            for (int p = 0; p < 2; ++p) {
                ull mu12 = MUL2(am1[p], am2[p]);
                ull mu1s = MUL2(am1[p], am1[p]);
                ull mu2s = MUL2(am2[p], am2[p]);
                ull s12  = FMA2(mu12, NEG1, aq12[p]);  // q12 - mu1*mu2
                ull n1   = FMA2(TWO2, mu12, C1v);
                ull n2   = FMA2(TWO2, s12,  C2v);
                ull aa   = ADD2(mu1s, mu2s);
                ull d1   = ADD2(aa, C1v);
                ull tt   = FMA2(aa, NEG1, aqs[p]);     // qs - (mu1^2+mu2^2)
                ull d2   = ADD2(tt, C2v);
                ull num  = MUL2(n1, n2);
                ull den  = MUL2(d1, d2);
                acc += __fdividef(FLO(num), FLO(den));
                acc += __fdividef(FHI(num), FHI(den));
            }
        }
    }

    // ================= Reduction =================
    #pragma unroll
    for (int o = 16; o; o >>= 1)
        acc += __shfl_xor_sync(0xFFFFFFFFu, acc, o);

    __shared__ float ws[NTHR / 32];
    if ((tid & 31) == 0) ws[tid >> 5] = acc;
    __syncthreads();

    const int bid = (blockIdx.z * GY + blockIdx.y) * GX + blockIdx.x;
    __shared__ unsigned int is_last;
    if (tid == 0) {
        float bs = 0.f;
        #pragma unroll
        for (int i = 0; i < NTHR / 32; ++i) bs += ws[i];
        __stcg(&g_partials[bid], bs);
        __threadfence();
        is_last = (atomicAdd(&g_count, 1u) == (unsigned)(NBLK - 1));
    }
    __syncthreads();

    if (is_last) {
        double s = 0.0;
        for (int i = tid; i < NBLK; i += NTHR)
            s += (double)__ldcg(&g_partials[i]);
        #pragma unroll
        for (int o = 16; o; o >>= 1)
            s += __shfl_xor_sync(0xFFFFFFFFu, s, o);
        __shared__ double wd[NTHR / 32];
        if ((tid & 31) == 0) wd[tid >> 5] = s;
        __syncthreads();
        if (tid == 0) {
            double bs = 0.0;
            #pragma unroll
            for (int i = 0; i < NTHR / 32; ++i) bs += wd[i];
            double n = (double)PLANES * HH * WW;
            out[0] = (float)(1.0 - bs / n);
            g_count = 0;   // reset for next graph replay
        }
    }
}

extern "C" void kernel_launch(void* const* d_in, const int* in_sizes, int n_in,
                              void* d_out, int out_size)
{
    (void)in_sizes; (void)n_in; (void)out_size;
    const float* img1 = (const float*)d_in[0];
    const float* img2 = (const float*)d_in[1];
    float* out = (float*)d_out;

    dim3 grid(GX, GY, PLANES);
    ssim_main<<<grid, NTHR>>>(img1, img2, out);
}